// round 15
// baseline (speedup 1.0000x reference)
#include <cuda_runtime.h>
#include <cuda_bf16.h>
#include <math.h>
#include <stdint.h>

#define NR 131072
#define D 512
#define D2 1024
#define MC 512

#define BM 128
#define BN 128
#define BK 64
#define STAGES 3
#define A_BYTES (BM * BK * 2)            // 16KB
#define B_BYTES (BN * BK * 2)            // 16KB
#define STAGE_BYTES (A_BYTES + B_BYTES)  // 32KB
#define SMEM_DYN (STAGES * STAGE_BYTES + 128)

typedef __nv_bfloat16 bf16;

// ---- scratch (device globals: allocation-free rule workaround) ----
__device__ __align__(16) bf16  g_xb[(size_t)NR * D];    // x bf16, later y bf16
__device__ __align__(16) float g_xf[(size_t)NR * D];    // x f32, later y f32
__device__ __align__(16) bf16  g_h [(size_t)NR * D2];   // hidden bf16 (k-permuted layout)
__device__ __align__(16) bf16  g_wup[(size_t)D2 * D];   // W_up^T  [n][k]
__device__ __align__(16) bf16  g_wdn[(size_t)D  * D2];  // W_down^T [n][perm(k)]
__device__ __align__(16) bf16  g_cb [(size_t)MC * D];   // codebook bf16 [n][k]
__device__ float g_cnorm[MC];

// =================== PTX helpers (sm_80-safe only) ===================
__device__ __forceinline__ uint32_t smem_u32(const void* p) {
    uint32_t a;
    asm("{.reg .u64 t; cvta.to.shared.u64 t, %1; cvt.u32.u64 %0, t;}" : "=r"(a) : "l"(p));
    return a;
}
__device__ __forceinline__ void cp16(uint32_t dst, const void* src) {
    asm volatile("{.reg .u64 g; cvta.to.global.u64 g, %1;"
                 "cp.async.cg.shared.global [%0], [g], 16;}"
                 :: "r"(dst), "l"(src) : "memory");
}
__device__ __forceinline__ void cp_commit() { asm volatile("cp.async.commit_group;" ::: "memory"); }
template <int N> __device__ __forceinline__ void cp_wait() {
    asm volatile("cp.async.wait_group %0;" :: "n"(N) : "memory");
}
__device__ __forceinline__ void ldsm4(unsigned& r0, unsigned& r1, unsigned& r2, unsigned& r3,
                                      uint32_t a) {
    asm volatile("ldmatrix.sync.aligned.m8n8.x4.shared.b16 {%0,%1,%2,%3}, [%4];"
                 : "=r"(r0), "=r"(r1), "=r"(r2), "=r"(r3) : "r"(a));
}
__device__ __forceinline__ void mma_bf16(float (&d)[4], const unsigned (&a)[4],
                                         const unsigned (&b)[2]) {
    asm volatile(
        "mma.sync.aligned.m16n8k16.row.col.f32.bf16.bf16.f32 "
        "{%0,%1,%2,%3}, {%4,%5,%6,%7}, {%8,%9}, {%0,%1,%2,%3};\n"
        : "+f"(d[0]), "+f"(d[1]), "+f"(d[2]), "+f"(d[3])
        : "r"(a[0]), "r"(a[1]), "r"(a[2]), "r"(a[3]), "r"(b[0]), "r"(b[1]));
}

// SW128 swizzle on byte offsets within a tile (rows of 128B)
#define SWZ(x) ((x) ^ (((x) >> 3) & 0x70))

// =================== stage loader: A[128xBK] + B[128xBK], bf16, 256 thr ==========
__device__ __forceinline__ void load_stage(uint32_t sA, uint32_t sB,
                                           const bf16* __restrict__ Ag, int lda, int m0, int k0,
                                           const bf16* __restrict__ Bg, int ldb, int n0,
                                           int tid) {
#pragma unroll
    for (int i = 0; i < 4; i++) {  // 128 rows x 8 segs of 16B
        int idx = tid + i * 256;
        int row = idx >> 3, seg = idx & 7;
        cp16(sA + SWZ(row * 128 + seg * 16), Ag + (size_t)(m0 + row) * lda + k0 + seg * 8);
    }
#pragma unroll
    for (int i = 0; i < 4; i++) {
        int idx = tid + i * 256;
        int row = idx >> 3, seg = idx & 7;
        cp16(sB + SWZ(row * 128 + seg * 16), Bg + (size_t)(n0 + row) * ldb + k0 + seg * 8);
    }
    cp_commit();
}

// =================== 128x128 GEMM, 8 warps of 32x64, multistage ===================
// B fragments double-buffered across k-steps; A loaded inline.
template <int NCHK>
__device__ __forceinline__ void gemm128(const bf16* __restrict__ Ag, int lda, int m0,
                                        const bf16* __restrict__ Bg, int ldb, int n0,
                                        uint32_t st0, float (&acc)[2][8][4]) {
    const int tid = threadIdx.x;
    const int lane = tid & 31, warp = tid >> 5;
    const int wm = warp >> 1, wn = warp & 1;

#pragma unroll
    for (int mt = 0; mt < 2; mt++)
#pragma unroll
        for (int nt = 0; nt < 8; nt++)
#pragma unroll
            for (int c = 0; c < 4; c++) acc[mt][nt][c] = 0.f;

    __syncthreads();  // smem reuse fence
#pragma unroll
    for (int s = 0; s < STAGES - 1; s++)
        load_stage(st0 + s * STAGE_BYTES, st0 + s * STAGE_BYTES + A_BYTES,
                   Ag, lda, m0, s * BK, Bg, ldb, n0, tid);

    const int arow = (lane & 7) | (((lane >> 3) & 1) << 3);
    const int acol = (lane >> 4) * 16;
    const int brow = (lane & 7) + ((lane >> 4) << 3);
    const int bcol = ((lane >> 3) & 1) * 16;

    unsigned b[2][8][2];

    for (int c = 0; c < NCHK; c++) {
        cp_wait<STAGES - 2>();
        __syncthreads();
        int nx = c + STAGES - 1;
        if (nx < NCHK) {
            int sx = nx % STAGES;
            load_stage(st0 + sx * STAGE_BYTES, st0 + sx * STAGE_BYTES + A_BYTES,
                       Ag, lda, m0, nx * BK, Bg, ldb, n0, tid);
        }
        int s = c % STAGES;
        uint32_t sA = st0 + s * STAGE_BYTES, sB = sA + A_BYTES;
        // preload B fragments for ks=0
#pragma unroll
        for (int p = 0; p < 4; p++) {
            unsigned r0, r1, r2, r3;
            ldsm4(r0, r1, r2, r3, sB + SWZ((wn * 64 + p * 16 + brow) * 128 + bcol));
            b[0][2 * p][0] = r0; b[0][2 * p][1] = r1;
            b[0][2 * p + 1][0] = r2; b[0][2 * p + 1][1] = r3;
        }
#pragma unroll
        for (int ks = 0; ks < BK / 16; ks++) {
            const int cur = ks & 1;
            unsigned a[2][4];
#pragma unroll
            for (int mt = 0; mt < 2; mt++)
                ldsm4(a[mt][0], a[mt][1], a[mt][2], a[mt][3],
                      sA + SWZ((wm * 32 + mt * 16 + arow) * 128 + ks * 32 + acol));
            if (ks < BK / 16 - 1) {  // prefetch next B fragments ahead of MMA stream
#pragma unroll
                for (int p = 0; p < 4; p++) {
                    unsigned r0, r1, r2, r3;
                    ldsm4(r0, r1, r2, r3,
                          sB + SWZ((wn * 64 + p * 16 + brow) * 128 + (ks + 1) * 32 + bcol));
                    b[cur ^ 1][2 * p][0] = r0; b[cur ^ 1][2 * p][1] = r1;
                    b[cur ^ 1][2 * p + 1][0] = r2; b[cur ^ 1][2 * p + 1][1] = r3;
                }
            }
#pragma unroll
            for (int mt = 0; mt < 2; mt++)
#pragma unroll
                for (int nt = 0; nt < 8; nt++) mma_bf16(acc[mt][nt], a[mt], b[cur][nt]);
        }
    }
    __syncthreads();
}

// ---------------- prep: transpose+cast weights (+ codebook norms) ----------------
// g_wdn uses k-permutation matching the up-phase coalesced h store:
//   within each 64-block: r = nt*8 + 2t + e  ->  rp = t*16 + nt*2 + e
__device__ __forceinline__ int permk(int k) {
    int r = k & 63;
    int nt = r >> 3, t = (r >> 1) & 3, e = r & 1;
    return (k & ~63) | (t * 16 + nt * 2 + e);
}

__global__ void k_prep(const float* __restrict__ wup, const float* __restrict__ wdn,
                       const float* __restrict__ mb) {
    int stride = gridDim.x * blockDim.x;
    int t0 = blockIdx.x * blockDim.x + threadIdx.x;
    for (int i = t0; i < D2 * D; i += stride) {
        int n = i / D, k = i % D;
        g_wup[i] = __float2bfloat16(wup[(size_t)k * D2 + n]);
    }
    for (int i = t0; i < D * D2; i += stride) {
        int n = i / D2, k = i % D2;
        g_wdn[(size_t)n * D2 + permk(k)] = __float2bfloat16(wdn[(size_t)k * D + n]);
    }
    for (int i = t0; i < MC * D; i += stride)
        g_cb[i] = __float2bfloat16(mb[i]);
    for (int c = t0; c < MC; c += stride) {
        const float* r = mb + (size_t)c * D;
        float s = 0.f;
        for (int k = 0; k < D; k++) s += r[k] * r[k];
        g_cnorm[c] = s;
    }
}

// ---------------- k1: x = in + 0.1*nb + mu ----------------
__global__ void k_x(const float4* __restrict__ in, const float4* __restrict__ nb,
                    const float4* __restrict__ mu) {
    size_t i = (size_t)blockIdx.x * blockDim.x + threadIdx.x;
    int c = (int)(i & (D / 4 - 1));
    float4 a = in[i], b = nb[i], m = mu[c];
    float4 x;
    x.x = a.x + 0.1f * b.x + m.x;
    x.y = a.y + 0.1f * b.y + m.y;
    x.z = a.z + 0.1f * b.z + m.z;
    x.w = a.w + 0.1f * b.w + m.w;
    ((float4*)g_xf)[i] = x;
    __nv_bfloat162 h0 = __floats2bfloat162_rn(x.x, x.y);
    __nv_bfloat162 h1 = __floats2bfloat162_rn(x.z, x.w);
    uint2 u;
    u.x = *reinterpret_cast<unsigned int*>(&h0);
    u.y = *reinterpret_cast<unsigned int*>(&h1);
    ((uint2*)g_xb)[i] = u;
}

// ---------------- up: h = silu(x @ Wup + b), permuted-coalesced store ----------------
__global__ __launch_bounds__(256, 2) void k_up(const float* __restrict__ bup) {
    extern __shared__ char dyn[];
    uint32_t st0 = (smem_u32(dyn) + 127u) & ~127u;
    float acc[2][8][4];
    int m0 = blockIdx.y * BM, n0 = blockIdx.x * BN;
    gemm128<D / BK>(g_xb, D, m0, g_wup, D, n0, st0, acc);

    const int lane = threadIdx.x & 31, warp = threadIdx.x >> 5;
    const int wm = warp >> 1, wn = warp & 1, g = lane >> 2, t = lane & 3;
    // thread's 16 values per (mt,h): cols nt*8+2t+e -> stored at col' = t*16+nt*2+e
#pragma unroll
    for (int mt = 0; mt < 2; mt++)
#pragma unroll
        for (int h = 0; h < 2; h++) {
            int row = m0 + wm * 32 + mt * 16 + g + h * 8;
            uint32_t pk[8];
#pragma unroll
            for (int nt = 0; nt < 8; nt++) {
                int col = n0 + wn * 64 + nt * 8 + 2 * t;
                float z0 = acc[mt][nt][h * 2 + 0] + __ldg(&bup[col]);
                float z1 = acc[mt][nt][h * 2 + 1] + __ldg(&bup[col + 1]);
                float s0 = z0 / (1.f + __expf(-z0));
                float s1 = z1 / (1.f + __expf(-z1));
                __nv_bfloat162 p = __floats2bfloat162_rn(s0, s1);
                pk[nt] = *reinterpret_cast<uint32_t*>(&p);
            }
            uint4* dst = (uint4*)&g_h[(size_t)row * D2 + n0 + wn * 64 + t * 16];
            dst[0] = make_uint4(pk[0], pk[1], pk[2], pk[3]);
            dst[1] = make_uint4(pk[4], pk[5], pk[6], pk[7]);
        }
}

// ---------------- helpers ----------------
__device__ __forceinline__ float fixv(float v) {
    if (isnan(v)) return 0.f;
    if (isinf(v)) return v > 0.f ? 1.f : -1.f;
    return v;
}

// ======== merged down + vq kernel: CTA owns row block end-to-end ========
__global__ __launch_bounds__(256, 2) void k_dnv(const float* __restrict__ bdn,
                                                const float* __restrict__ gate,
                                                const float* __restrict__ mb,
                                                float* __restrict__ out) {
    extern __shared__ char dyn[];
    uint32_t st0 = (smem_u32(dyn) + 127u) & ~127u;
    __shared__ unsigned long long best[128];
    __shared__ float s_cn[MC];
    const int tid = threadIdx.x;
    const int lane = tid & 31, warp = tid >> 5;
    const int wm = warp >> 1, wn = warp & 1, g = lane >> 2, t = lane & 3;
    const int m0 = blockIdx.x * BM;

    for (int i = tid; i < MC; i += 256) s_cn[i] = g_cnorm[i];
    if (tid < 128) best[tid] = 0xFFFFFFFFFFFFFFFFULL;

    // -------- phase D: y = x + (h @ Wdn + b)*tanh(gate), all 4 n-tiles --------
    float gt = tanhf(gate[0]);
#pragma unroll 1
    for (int ntile = 0; ntile < D / BN; ntile++) {
        int n0 = ntile * BN;
        float acc[2][8][4];
        gemm128<D2 / BK>(g_h, D2, m0, g_wdn, D2, n0, st0, acc);
#pragma unroll
        for (int mt = 0; mt < 2; mt++)
#pragma unroll
            for (int nt = 0; nt < 8; nt++)
#pragma unroll
                for (int h = 0; h < 2; h++) {
                    int row = m0 + wm * 32 + mt * 16 + g + h * 8;
                    int col = n0 + wn * 64 + nt * 8 + 2 * t;
                    size_t o = (size_t)row * D + col;
                    float y0 = g_xf[o]     + (acc[mt][nt][h * 2 + 0] + __ldg(&bdn[col]))     * gt;
                    float y1 = g_xf[o + 1] + (acc[mt][nt][h * 2 + 1] + __ldg(&bdn[col + 1])) * gt;
                    g_xf[o] = y0;
                    g_xf[o + 1] = y1;
                    __nv_bfloat162 p = __floats2bfloat162_rn(y0, y1);
                    *reinterpret_cast<__nv_bfloat162*>(&g_xb[o]) = p;
                }
    }
    __threadfence();  // publish y (fp32+bf16) before cp.async L2 reads in phase V

    // -------- phase V: VQ argmin over codebook (y is L2-hot, same CTA) --------
#pragma unroll 1
    for (int nt4 = 0; nt4 < MC / BN; nt4++) {
        float acc[2][8][4];
        gemm128<D / BK>(g_xb, D, m0, g_cb, D, nt4 * BN, st0, acc);
#pragma unroll
        for (int mt = 0; mt < 2; mt++)
#pragma unroll
            for (int h = 0; h < 2; h++) {
                int rloc = wm * 32 + mt * 16 + g + h * 8;
                float bs = __int_as_float(0x7f800000);
                int bi = 0;
#pragma unroll
                for (int nt = 0; nt < 8; nt++)
#pragma unroll
                    for (int c = 0; c < 2; c++) {
                        int col = nt4 * BN + wn * 64 + nt * 8 + 2 * t + c;
                        float s = -2.f * acc[mt][nt][h * 2 + c] + s_cn[col];
                        if (s < bs) { bs = s; bi = col; }
                    }
                unsigned k = __float_as_uint(bs);
                k = (k & 0x80000000u) ? ~k : (k | 0x80000000u);
                unsigned long long packed = ((unsigned long long)k << 32) | (unsigned)bi;
                atomicMin(&best[rloc], packed);
            }
    }
    __syncthreads();

    // -------- phase E: gather + nan fix + norm clamp --------
    for (int rr = warp; rr < 128; rr += 8) {
        int row = m0 + rr;
        int ci = (int)(best[rr] & 0xFFFFFFFFu);
        const float4* crow = (const float4*)(mb + (size_t)ci * D);
        const float4* yrow = (const float4*)(g_xf + (size_t)row * D);
        float4 v[4];
        float ss = 0.f;
#pragma unroll
        for (int j = 0; j < 4; j++) {
            int c4 = j * 32 + lane;
            float4 y = yrow[c4], c = crow[c4];
            float4 x;
            x.x = fixv(y.x + 0.05f * c.x);
            x.y = fixv(y.y + 0.05f * c.y);
            x.z = fixv(y.z + 0.05f * c.z);
            x.w = fixv(y.w + 0.05f * c.w);
            ss += x.x * x.x + x.y * x.y + x.z * x.z + x.w * x.w;
            v[j] = x;
        }
#pragma unroll
        for (int o = 16; o > 0; o >>= 1) ss += __shfl_xor_sync(0xffffffffu, ss, o);
        float nrm = sqrtf(ss);
        float scale = (nrm > 10.f) ? (10.f / fmaxf(nrm, 1e-6f)) : 1.f;
        float4* orow = (float4*)(out + (size_t)row * D);
#pragma unroll
        for (int j = 0; j < 4; j++) {
            float4 x = v[j];
            x.x *= scale; x.y *= scale; x.z *= scale; x.w *= scale;
            orow[j * 32 + lane] = x;
        }
    }
}

// ---------------- launch ----------------
extern "C" void kernel_launch(void* const* d_in, const int* in_sizes, int n_in,
                              void* d_out, int out_size) {
    const float* in_emb = (const float*)d_in[0];
    const float* neigh  = (const float*)d_in[1];
    const float* mu     = (const float*)d_in[2];
    const float* wup    = (const float*)d_in[3];
    const float* bup    = (const float*)d_in[4];
    const float* wdn    = (const float*)d_in[5];
    const float* bdn    = (const float*)d_in[6];
    const float* gate   = (const float*)d_in[7];
    const float* mb     = (const float*)d_in[8];
    float* out = (float*)d_out;

    static bool attr_done = false;
    if (!attr_done) {
        cudaFuncSetAttribute(k_up, cudaFuncAttributeMaxDynamicSharedMemorySize, SMEM_DYN);
        cudaFuncSetAttribute(k_dnv, cudaFuncAttributeMaxDynamicSharedMemorySize, SMEM_DYN);
        attr_done = true;
    }

    k_prep<<<512, 256>>>(wup, wdn, mb);
    k_x<<<(NR * D / 4) / 256, 256>>>((const float4*)in_emb, (const float4*)neigh,
                                     (const float4*)mu);
    k_up<<<dim3(D2 / BN, NR / BM), 256, SMEM_DYN>>>(bup);
    k_dnv<<<NR / BM, 256, SMEM_DYN>>>(bdn, gate, mb, out);
}

// round 16
// speedup vs baseline: 1.3133x; 1.3133x over previous
#include <cuda_runtime.h>
#include <cuda_bf16.h>
#include <math.h>
#include <stdint.h>

#define NR 131072
#define D 512
#define D2 1024
#define MC 512

#define BM 128
#define BN 128
#define BK 64
#define STAGES 3
#define A_BYTES (BM * BK * 2)            // 16KB
#define B_BYTES (BN * BK * 2)            // 16KB
#define STAGE_BYTES (A_BYTES + B_BYTES)  // 32KB
#define SMEM_DYN (STAGES * STAGE_BYTES + 128)

#define PREP_BLOCKS 512
#define X_BLOCKS ((NR * D / 4) / 256)    // 65536

typedef __nv_bfloat16 bf16;

// ---- scratch (device globals: allocation-free rule workaround) ----
__device__ __align__(16) bf16  g_xb[(size_t)NR * D];    // x bf16, later y bf16
__device__ __align__(16) float g_xf[(size_t)NR * D];    // x f32, later y f32
__device__ __align__(16) bf16  g_h [(size_t)NR * D2];   // hidden bf16 (k-permuted layout)
__device__ __align__(16) bf16  g_wup[(size_t)D2 * D];   // W_up^T  [n][k]
__device__ __align__(16) bf16  g_wdn[(size_t)D  * D2];  // W_down^T [n][perm(k)]
__device__ __align__(16) bf16  g_cb [(size_t)MC * D];   // codebook bf16 [n][k]
__device__ float g_cnorm[MC];

// =================== PTX helpers (sm_80-safe only) ===================
__device__ __forceinline__ uint32_t smem_u32(const void* p) {
    uint32_t a;
    asm("{.reg .u64 t; cvta.to.shared.u64 t, %1; cvt.u32.u64 %0, t;}" : "=r"(a) : "l"(p));
    return a;
}
__device__ __forceinline__ void cp16(uint32_t dst, const void* src) {
    asm volatile("{.reg .u64 g; cvta.to.global.u64 g, %1;"
                 "cp.async.cg.shared.global [%0], [g], 16;}"
                 :: "r"(dst), "l"(src) : "memory");
}
__device__ __forceinline__ void cp_commit() { asm volatile("cp.async.commit_group;" ::: "memory"); }
template <int N> __device__ __forceinline__ void cp_wait() {
    asm volatile("cp.async.wait_group %0;" :: "n"(N) : "memory");
}
__device__ __forceinline__ void ldsm4(unsigned& r0, unsigned& r1, unsigned& r2, unsigned& r3,
                                      uint32_t a) {
    asm volatile("ldmatrix.sync.aligned.m8n8.x4.shared.b16 {%0,%1,%2,%3}, [%4];"
                 : "=r"(r0), "=r"(r1), "=r"(r2), "=r"(r3) : "r"(a));
}
__device__ __forceinline__ void mma_bf16(float (&d)[4], const unsigned (&a)[4],
                                         const unsigned (&b)[2]) {
    asm volatile(
        "mma.sync.aligned.m16n8k16.row.col.f32.bf16.bf16.f32 "
        "{%0,%1,%2,%3}, {%4,%5,%6,%7}, {%8,%9}, {%0,%1,%2,%3};\n"
        : "+f"(d[0]), "+f"(d[1]), "+f"(d[2]), "+f"(d[3])
        : "r"(a[0]), "r"(a[1]), "r"(a[2]), "r"(a[3]), "r"(b[0]), "r"(b[1]));
}

// SW128 swizzle on byte offsets within a tile (rows of 128B)
#define SWZ(x) ((x) ^ (((x) >> 3) & 0x70))

// =================== stage loader: A[128xBK] + B[128xBK], bf16, 256 thr ==========
__device__ __forceinline__ void load_stage(uint32_t sA, uint32_t sB,
                                           const bf16* __restrict__ Ag, int lda, int m0, int k0,
                                           const bf16* __restrict__ Bg, int ldb, int n0,
                                           int tid) {
#pragma unroll
    for (int i = 0; i < 4; i++) {  // 128 rows x 8 segs of 16B
        int idx = tid + i * 256;
        int row = idx >> 3, seg = idx & 7;
        cp16(sA + SWZ(row * 128 + seg * 16), Ag + (size_t)(m0 + row) * lda + k0 + seg * 8);
    }
#pragma unroll
    for (int i = 0; i < 4; i++) {
        int idx = tid + i * 256;
        int row = idx >> 3, seg = idx & 7;
        cp16(sB + SWZ(row * 128 + seg * 16), Bg + (size_t)(n0 + row) * ldb + k0 + seg * 8);
    }
    cp_commit();
}

// =================== 128x128 GEMM, 8 warps of 32x64, multistage ===================
// B fragments double-buffered across k-steps; A loaded inline.
template <int NCHK>
__device__ __forceinline__ void gemm128(const bf16* __restrict__ Ag, int lda, int m0,
                                        const bf16* __restrict__ Bg, int ldb, int n0,
                                        uint32_t st0, float (&acc)[2][8][4]) {
    const int tid = threadIdx.x;
    const int lane = tid & 31, warp = tid >> 5;
    const int wm = warp >> 1, wn = warp & 1;

#pragma unroll
    for (int mt = 0; mt < 2; mt++)
#pragma unroll
        for (int nt = 0; nt < 8; nt++)
#pragma unroll
            for (int c = 0; c < 4; c++) acc[mt][nt][c] = 0.f;

    __syncthreads();  // smem reuse fence
#pragma unroll
    for (int s = 0; s < STAGES - 1; s++)
        load_stage(st0 + s * STAGE_BYTES, st0 + s * STAGE_BYTES + A_BYTES,
                   Ag, lda, m0, s * BK, Bg, ldb, n0, tid);

    const int arow = (lane & 7) | (((lane >> 3) & 1) << 3);
    const int acol = (lane >> 4) * 16;
    const int brow = (lane & 7) + ((lane >> 4) << 3);
    const int bcol = ((lane >> 3) & 1) * 16;

    unsigned b[2][8][2];

    for (int c = 0; c < NCHK; c++) {
        cp_wait<STAGES - 2>();
        __syncthreads();
        int nx = c + STAGES - 1;
        if (nx < NCHK) {
            int sx = nx % STAGES;
            load_stage(st0 + sx * STAGE_BYTES, st0 + sx * STAGE_BYTES + A_BYTES,
                       Ag, lda, m0, nx * BK, Bg, ldb, n0, tid);
        }
        int s = c % STAGES;
        uint32_t sA = st0 + s * STAGE_BYTES, sB = sA + A_BYTES;
        // preload B fragments for ks=0
#pragma unroll
        for (int p = 0; p < 4; p++) {
            unsigned r0, r1, r2, r3;
            ldsm4(r0, r1, r2, r3, sB + SWZ((wn * 64 + p * 16 + brow) * 128 + bcol));
            b[0][2 * p][0] = r0; b[0][2 * p][1] = r1;
            b[0][2 * p + 1][0] = r2; b[0][2 * p + 1][1] = r3;
        }
#pragma unroll
        for (int ks = 0; ks < BK / 16; ks++) {
            const int cur = ks & 1;
            unsigned a[2][4];
#pragma unroll
            for (int mt = 0; mt < 2; mt++)
                ldsm4(a[mt][0], a[mt][1], a[mt][2], a[mt][3],
                      sA + SWZ((wm * 32 + mt * 16 + arow) * 128 + ks * 32 + acol));
            if (ks < BK / 16 - 1) {  // prefetch next B fragments ahead of MMA stream
#pragma unroll
                for (int p = 0; p < 4; p++) {
                    unsigned r0, r1, r2, r3;
                    ldsm4(r0, r1, r2, r3,
                          sB + SWZ((wn * 64 + p * 16 + brow) * 128 + (ks + 1) * 32 + bcol));
                    b[cur ^ 1][2 * p][0] = r0; b[cur ^ 1][2 * p][1] = r1;
                    b[cur ^ 1][2 * p + 1][0] = r2; b[cur ^ 1][2 * p + 1][1] = r3;
                }
            }
#pragma unroll
            for (int mt = 0; mt < 2; mt++)
#pragma unroll
                for (int nt = 0; nt < 8; nt++) mma_bf16(acc[mt][nt], a[mt], b[cur][nt]);
        }
    }
    __syncthreads();
}

// ---------------- merged prep + x kernel ----------------
// blocks [0, PREP_BLOCKS): transpose+cast weights, codebook, norms
//   (original k_prep logic & stride, hidden under the DRAM-bound x blocks)
// blocks [PREP_BLOCKS, PREP_BLOCKS+X_BLOCKS): x = in + 0.1*nb + mu
// g_wdn uses k-permutation matching the up-phase coalesced h store:
//   within each 64-block: r = nt*8 + 2t + e  ->  rp = t*16 + nt*2 + e
__device__ __forceinline__ int permk(int k) {
    int r = k & 63;
    int nt = r >> 3, t = (r >> 1) & 3, e = r & 1;
    return (k & ~63) | (t * 16 + nt * 2 + e);
}

__global__ void k_px(const float* __restrict__ wup, const float* __restrict__ wdn,
                     const float* __restrict__ mb,
                     const float4* __restrict__ in, const float4* __restrict__ nb,
                     const float4* __restrict__ mu) {
    if (blockIdx.x < PREP_BLOCKS) {
        const int stride = PREP_BLOCKS * 256;
        int t0 = blockIdx.x * 256 + threadIdx.x;
        for (int i = t0; i < D2 * D; i += stride) {
            int n = i / D, k = i % D;
            g_wup[i] = __float2bfloat16(wup[(size_t)k * D2 + n]);
        }
        for (int i = t0; i < D * D2; i += stride) {
            int n = i / D2, k = i % D2;
            g_wdn[(size_t)n * D2 + permk(k)] = __float2bfloat16(wdn[(size_t)k * D + n]);
        }
        for (int i = t0; i < MC * D; i += stride)
            g_cb[i] = __float2bfloat16(mb[i]);
        for (int c = t0; c < MC; c += stride) {
            const float* r = mb + (size_t)c * D;
            float s = 0.f;
            for (int k = 0; k < D; k++) s += r[k] * r[k];
            g_cnorm[c] = s;
        }
        return;
    }
    size_t i = (size_t)(blockIdx.x - PREP_BLOCKS) * 256 + threadIdx.x;
    int c = (int)(i & (D / 4 - 1));
    float4 a = in[i], b = nb[i], m = mu[c];
    float4 x;
    x.x = a.x + 0.1f * b.x + m.x;
    x.y = a.y + 0.1f * b.y + m.y;
    x.z = a.z + 0.1f * b.z + m.z;
    x.w = a.w + 0.1f * b.w + m.w;
    ((float4*)g_xf)[i] = x;
    __nv_bfloat162 h0 = __floats2bfloat162_rn(x.x, x.y);
    __nv_bfloat162 h1 = __floats2bfloat162_rn(x.z, x.w);
    uint2 u;
    u.x = *reinterpret_cast<unsigned int*>(&h0);
    u.y = *reinterpret_cast<unsigned int*>(&h1);
    ((uint2*)g_xb)[i] = u;
}

// ---------------- up: h = silu(x @ Wup + b), permuted-coalesced store ----------------
__global__ __launch_bounds__(256, 2) void k_up(const float* __restrict__ bup) {
    extern __shared__ char dyn[];
    uint32_t st0 = (smem_u32(dyn) + 127u) & ~127u;
    float acc[2][8][4];
    int m0 = blockIdx.y * BM, n0 = blockIdx.x * BN;
    gemm128<D / BK>(g_xb, D, m0, g_wup, D, n0, st0, acc);

    const int lane = threadIdx.x & 31, warp = threadIdx.x >> 5;
    const int wm = warp >> 1, wn = warp & 1, g = lane >> 2, t = lane & 3;
    // thread's 16 values per (mt,h): cols nt*8+2t+e -> stored at col' = t*16+nt*2+e
#pragma unroll
    for (int mt = 0; mt < 2; mt++)
#pragma unroll
        for (int h = 0; h < 2; h++) {
            int row = m0 + wm * 32 + mt * 16 + g + h * 8;
            uint32_t pk[8];
#pragma unroll
            for (int nt = 0; nt < 8; nt++) {
                int col = n0 + wn * 64 + nt * 8 + 2 * t;
                float z0 = acc[mt][nt][h * 2 + 0] + __ldg(&bup[col]);
                float z1 = acc[mt][nt][h * 2 + 1] + __ldg(&bup[col + 1]);
                float s0 = z0 / (1.f + __expf(-z0));
                float s1 = z1 / (1.f + __expf(-z1));
                __nv_bfloat162 p = __floats2bfloat162_rn(s0, s1);
                pk[nt] = *reinterpret_cast<uint32_t*>(&p);
            }
            uint4* dst = (uint4*)&g_h[(size_t)row * D2 + n0 + wn * 64 + t * 16];
            dst[0] = make_uint4(pk[0], pk[1], pk[2], pk[3]);
            dst[1] = make_uint4(pk[4], pk[5], pk[6], pk[7]);
        }
}

// ---------------- down: y = x + (h @ Wdn + b)*tanh(g) ----------------
__global__ __launch_bounds__(256, 2) void k_dn(const float* __restrict__ bdn,
                                               const float* __restrict__ gate) {
    extern __shared__ char dyn[];
    uint32_t st0 = (smem_u32(dyn) + 127u) & ~127u;
    float acc[2][8][4];
    int m0 = blockIdx.y * BM, n0 = blockIdx.x * BN;
    gemm128<D2 / BK>(g_h, D2, m0, g_wdn, D2, n0, st0, acc);

    float gt = tanhf(gate[0]);
    const int lane = threadIdx.x & 31, warp = threadIdx.x >> 5;
    const int wm = warp >> 1, wn = warp & 1, g = lane >> 2, t = lane & 3;
#pragma unroll
    for (int mt = 0; mt < 2; mt++)
#pragma unroll
        for (int nt = 0; nt < 8; nt++)
#pragma unroll
            for (int h = 0; h < 2; h++) {
                int row = m0 + wm * 32 + mt * 16 + g + h * 8;
                int col = n0 + wn * 64 + nt * 8 + 2 * t;
                size_t o = (size_t)row * D + col;
                float y0 = g_xf[o]     + (acc[mt][nt][h * 2 + 0] + __ldg(&bdn[col]))     * gt;
                float y1 = g_xf[o + 1] + (acc[mt][nt][h * 2 + 1] + __ldg(&bdn[col + 1])) * gt;
                g_xf[o] = y0;
                g_xf[o + 1] = y1;
                __nv_bfloat162 p = __floats2bfloat162_rn(y0, y1);
                *reinterpret_cast<__nv_bfloat162*>(&g_xb[o]) = p;
            }
}

// ---------------- vq: argmin + memory add + nan fix + clamp ----------------
__device__ __forceinline__ float fixv(float v) {
    if (isnan(v)) return 0.f;
    if (isinf(v)) return v > 0.f ? 1.f : -1.f;
    return v;
}

__global__ __launch_bounds__(256, 2) void k_vq(const float* __restrict__ mb,
                                               float* __restrict__ out) {
    extern __shared__ char dyn[];
    uint32_t st0 = (smem_u32(dyn) + 127u) & ~127u;
    __shared__ unsigned long long best[128];
    __shared__ float s_cn[MC];
    const int tid = threadIdx.x;
    const int lane = tid & 31, warp = tid >> 5;
    const int wm = warp >> 1, wn = warp & 1, g = lane >> 2, t = lane & 3;

    for (int i = tid; i < MC; i += 256) s_cn[i] = g_cnorm[i];
    if (tid < 128) best[tid] = 0xFFFFFFFFFFFFFFFFULL;

    int m0 = blockIdx.x * BM;
    for (int nt4 = 0; nt4 < MC / BN; nt4++) {
        float acc[2][8][4];
        gemm128<D / BK>(g_xb, D, m0, g_cb, D, nt4 * BN, st0, acc);
#pragma unroll
        for (int mt = 0; mt < 2; mt++)
#pragma unroll
            for (int h = 0; h < 2; h++) {
                int rloc = wm * 32 + mt * 16 + g + h * 8;
                float bs = __int_as_float(0x7f800000);
                int bi = 0;
#pragma unroll
                for (int nt = 0; nt < 8; nt++)
#pragma unroll
                    for (int c = 0; c < 2; c++) {
                        int col = nt4 * BN + wn * 64 + nt * 8 + 2 * t + c;
                        float s = -2.f * acc[mt][nt][h * 2 + c] + s_cn[col];
                        if (s < bs) { bs = s; bi = col; }
                    }
                unsigned k = __float_as_uint(bs);
                k = (k & 0x80000000u) ? ~k : (k | 0x80000000u);
                unsigned long long packed = ((unsigned long long)k << 32) | (unsigned)bi;
                atomicMin(&best[rloc], packed);
            }
    }
    __syncthreads();

    // gather + epilogue: warp per row, 16 rows/warp
    for (int rr = warp; rr < 128; rr += 8) {
        int row = m0 + rr;
        int ci = (int)(best[rr] & 0xFFFFFFFFu);
        const float4* crow = (const float4*)(mb + (size_t)ci * D);
        const float4* yrow = (const float4*)(g_xf + (size_t)row * D);
        float4 v[4];
        float ss = 0.f;
#pragma unroll
        for (int j = 0; j < 4; j++) {
            int c4 = j * 32 + lane;
            float4 y = yrow[c4], c = crow[c4];
            float4 x;
            x.x = fixv(y.x + 0.05f * c.x);
            x.y = fixv(y.y + 0.05f * c.y);
            x.z = fixv(y.z + 0.05f * c.z);
            x.w = fixv(y.w + 0.05f * c.w);
            ss += x.x * x.x + x.y * x.y + x.z * x.z + x.w * x.w;
            v[j] = x;
        }
#pragma unroll
        for (int o = 16; o > 0; o >>= 1) ss += __shfl_xor_sync(0xffffffffu, ss, o);
        float nrm = sqrtf(ss);
        float scale = (nrm > 10.f) ? (10.f / fmaxf(nrm, 1e-6f)) : 1.f;
        float4* orow = (float4*)(out + (size_t)row * D);
#pragma unroll
        for (int j = 0; j < 4; j++) {
            float4 x = v[j];
            x.x *= scale; x.y *= scale; x.z *= scale; x.w *= scale;
            orow[j * 32 + lane] = x;
        }
    }
}

// ---------------- launch ----------------
extern "C" void kernel_launch(void* const* d_in, const int* in_sizes, int n_in,
                              void* d_out, int out_size) {
    const float* in_emb = (const float*)d_in[0];
    const float* neigh  = (const float*)d_in[1];
    const float* mu     = (const float*)d_in[2];
    const float* wup    = (const float*)d_in[3];
    const float* bup    = (const float*)d_in[4];
    const float* wdn    = (const float*)d_in[5];
    const float* bdn    = (const float*)d_in[6];
    const float* gate   = (const float*)d_in[7];
    const float* mb     = (const float*)d_in[8];
    float* out = (float*)d_out;

    static bool attr_done = false;
    if (!attr_done) {
        cudaFuncSetAttribute(k_up, cudaFuncAttributeMaxDynamicSharedMemorySize, SMEM_DYN);
        cudaFuncSetAttribute(k_dn, cudaFuncAttributeMaxDynamicSharedMemorySize, SMEM_DYN);
        cudaFuncSetAttribute(k_vq, cudaFuncAttributeMaxDynamicSharedMemorySize, SMEM_DYN);
        attr_done = true;
    }

    k_px<<<PREP_BLOCKS + X_BLOCKS, 256>>>(wup, wdn, mb, (const float4*)in_emb,
                                          (const float4*)neigh, (const float4*)mu);
    k_up<<<dim3(D2 / BN, NR / BM), 256, SMEM_DYN>>>(bup);
    k_dn<<<dim3(D / BN, NR / BM), 256, SMEM_DYN>>>(bdn, gate);
    k_vq<<<NR / BM, 256, SMEM_DYN>>>(mb, out);
}